// round 14
// baseline (speedup 1.0000x reference)
#include <cuda_runtime.h>
#include <math.h>

#define Td 32
#define Bd 8
#define Id 512
#define Hd 512
#define H3 1536
#define NBLK 256

// ---- output layout (concatenated tuple: v, h, dU, te, tE, outs) ----
#define OFF_V    0
#define OFF_H    4096
#define OFF_DU   8192
#define OFF_TE   2105344
#define OFF_TEE  2109440
#define OFF_OUTS 4206592

// ---- scratch (device globals; no allocation allowed) ----
__device__ float g_xproj[Td * Bd * H3]; // 1.5 MB (middle third unused)
__device__ float g_hbuf[2][Bd * Hd];    // ping-pong hidden state
__device__ unsigned g_count = 0;
__device__ unsigned g_flag[16 * 32];    // 16 broadcast flags, 128B apart
__device__ float g_gates[4][32];        // rotating gate accumulators [t&3][b*4+g]

// ============================================================
// xproj for z and dv chunks only (r chunk is dead in the reference).
// ============================================================
__global__ void __launch_bounds__(256) k_xproj(const float* __restrict__ x,
                                               const float* __restrict__ x2h_v,
                                               const float* __restrict__ x2h_g,
                                               const float* __restrict__ x2h_b) {
    __shared__ float xs[8 * 512]; // 16 KB
    int n = (blockIdx.x < 2) ? (blockIdx.x * 256 + threadIdx.x)
                             : (1024 + (blockIdx.x - 2) * 256 + threadIdx.x);
    int m0 = blockIdx.y * 8;
    for (int idx = threadIdx.x; idx < 8 * 512; idx += 256)
        xs[idx] = x[(m0 + (idx >> 9)) * 512 + (idx & 511)];
    __syncthreads();
    float acc[8];
#pragma unroll
    for (int m = 0; m < 8; m++) acc[m] = 0.f;
    float ss = 0.f;
    const float4* wrow4 = (const float4*)(x2h_v + n * 512);
#pragma unroll 2
    for (int c = 0; c < 128; c++) {
        float4 w4 = wrow4[c];
        ss = fmaf(w4.x, w4.x, ss); ss = fmaf(w4.y, w4.y, ss);
        ss = fmaf(w4.z, w4.z, ss); ss = fmaf(w4.w, w4.w, ss);
#pragma unroll
        for (int m = 0; m < 8; m++) {
            float4 x4 = ((const float4*)(xs + m * 512))[c];
            acc[m] = fmaf(w4.x, x4.x, acc[m]);
            acc[m] = fmaf(w4.y, x4.y, acc[m]);
            acc[m] = fmaf(w4.z, x4.z, acc[m]);
            acc[m] = fmaf(w4.w, x4.w, acc[m]);
        }
    }
    float sc = x2h_g[n] * rsqrtf(ss);
    float bb = x2h_b[n];
#pragma unroll
    for (int m = 0; m < 8; m++)
        g_xproj[(m0 + m) * H3 + n] = fmaf(acc[m], sc, bb);
}

// ============================================================
// Grid-wide software barrier (NBLK participants).
// ============================================================
__device__ __forceinline__ void grid_bar(unsigned &lgen, int fidx) {
    __syncthreads();
    __threadfence();
    if (threadIdx.x == 0) {
        unsigned a = atomicAdd(&g_count, 1u);
        if (a == NBLK - 1u) {
            g_count = 0u;
            __threadfence();
#pragma unroll
            for (int f = 0; f < 16; f++)
                ((volatile unsigned*)g_flag)[f * 32] = lgen + 1u;
        } else {
            volatile unsigned* vf = &g_flag[fidx * 32];
            while (*vf == lgen) { }
        }
        lgen += 1u;
    }
    __syncthreads();
}

__device__ __forceinline__ float sigf(float x) { return 1.f / (1.f + __expf(-x)); }
__device__ __forceinline__ float sshr(float y) {
    return (y > 0.5f) ? y - 0.5f : ((y < -0.5f) ? y + 0.5f : 0.f);
}

// ============================================================
// Persistent scan: 256 blocks own 2 rows each (iA=blk, iB=blk+256).
// Thread-private register state: te, hj, row-B dU/tE (64 regs).
// Everything else (weights, per-row constants, xproj) lives in SMEM so
// peak register liveness stays under the 128-reg cap (no spills).
// ============================================================
__global__ void __launch_bounds__(256, 2) k_scan(
    const float* __restrict__ h0, const float* __restrict__ v0,
    const float* __restrict__ dU0, const float* __restrict__ te0,
    const float* __restrict__ tE0, const float* __restrict__ alpha,
    const float* __restrict__ h2h_v, const float* __restrict__ h2h_g,
    const float* __restrict__ h2h_b, const float* __restrict__ h2mod_w,
    const float* __restrict__ h2mod_b, const float* __restrict__ modU_w,
    const float* __restrict__ modU_b, float* __restrict__ out)
{
    extern __shared__ float sm[];
    float* sdU   = sm;             // 4096 (row A dU)
    float* stE   = sdU + 4096;     // 4096 (row A tE)
    float* s_xp  = stE + 4096;     // 1024: [m][{zA,dA,zB,dB}]
    float* s_wvA = s_xp + 1024;    // 512
    float* s_bvA = s_wvA + 512;    // 512
    float* s_wvB = s_bvA + 512;    // 512
    float* s_bvB = s_wvB + 512;    // 512
    float* s_wzA = s_bvB + 512;    // 512
    float* s_wdA = s_wzA + 512;    // 512
    float* s_wzB = s_wdA + 512;    // 512
    float* s_wdB = s_wzB + 512;    // 512
    float* s_alA = s_wdB + 512;    // 512
    float* s_alB = s_alA + 512;    // 512
    float* s_loA = s_alB + 512;    // 512
    float* s_loB = s_loA + 512;    // 512
    float* s_upA = s_loB + 512;    // 512
    float* s_upB = s_upA + 512;    // 512
    // total 16384 floats = 65536 B

    __shared__ float sv[16], s_dvacc[16];
    __shared__ float s_hniA[8], s_hniB[8], s_teiA[8], s_teiB[8];
    __shared__ float s_g[32];
    __shared__ float s_redA[8][16], s_redB[8][16];
    __shared__ float s_sc[6];
    __shared__ float s_mw8[8], s_mb[4], s_bias[4];

    const int iA = blockIdx.x, iB = iA + 256;
    const int tid = threadIdx.x;
    const int wb = tid >> 5, lane = tid & 31;
    const int fidx = blockIdx.x & 15;
    unsigned lgen = ((volatile unsigned*)g_flag)[fidx * 32];

    if (tid < 8) s_mw8[tid] = h2mod_w[(tid & 3) * 512 + ((tid < 4) ? iA : iB)];
    if (tid < 4) s_mb[tid] = h2mod_b[tid];
    if (tid == 0) {
        s_bias[0] = h2h_b[iA];
        s_bias[1] = h2h_b[2 * Hd + iA];
        s_bias[2] = h2h_b[iB];
        s_bias[3] = h2h_b[2 * Hd + iB];
    }

    // ---- preload all 1024 xproj scalars this block needs ----
    {
        const float* xp = g_xproj + tid * H3;
        s_xp[tid * 4 + 0] = xp[iA];
        s_xp[tid * 4 + 1] = xp[2 * Hd + iA];
        s_xp[tid * 4 + 2] = xp[iB];
        s_xp[tid * 4 + 3] = xp[2 * Hd + iB];
    }

    // ---- inline weight-norm: 6 h2h rows (z/r/d for iA and iB) ----
    float2 vzA = ((const float2*)(h2h_v + iA * Hd))[tid];
    float2 vrA = ((const float2*)(h2h_v + (Hd + iA) * Hd))[tid];
    float2 vdA = ((const float2*)(h2h_v + (2 * Hd + iA) * Hd))[tid];
    float2 vzB = ((const float2*)(h2h_v + iB * Hd))[tid];
    float2 vrB = ((const float2*)(h2h_v + (Hd + iB) * Hd))[tid];
    float2 vdB = ((const float2*)(h2h_v + (2 * Hd + iB) * Hd))[tid];
    {
        float s0 = vzA.x * vzA.x + vzA.y * vzA.y;
        float s1 = vrA.x * vrA.x + vrA.y * vrA.y;
        float s2 = vdA.x * vdA.x + vdA.y * vdA.y;
        float s3 = vzB.x * vzB.x + vzB.y * vzB.y;
        float s4 = vrB.x * vrB.x + vrB.y * vrB.y;
        float s5 = vdB.x * vdB.x + vdB.y * vdB.y;
#pragma unroll
        for (int o = 16; o; o >>= 1) {
            s0 += __shfl_xor_sync(0xffffffffu, s0, o);
            s1 += __shfl_xor_sync(0xffffffffu, s1, o);
            s2 += __shfl_xor_sync(0xffffffffu, s2, o);
            s3 += __shfl_xor_sync(0xffffffffu, s3, o);
            s4 += __shfl_xor_sync(0xffffffffu, s4, o);
            s5 += __shfl_xor_sync(0xffffffffu, s5, o);
        }
        if (lane == 0) {
            s_redA[wb][0] = s0; s_redA[wb][1] = s1; s_redA[wb][2] = s2;
            s_redA[wb][3] = s3; s_redA[wb][4] = s4; s_redA[wb][5] = s5;
        }
    }
    __syncthreads();
    if (tid < 6) {
        float s = 0.f;
#pragma unroll
        for (int w2 = 0; w2 < 8; w2++) s += s_redA[w2][tid];
        int col = (tid < 3) ? iA : iB;
        int row = (tid % 3) * Hd + col;
        s_sc[tid] = h2h_g[row] * rsqrtf(s);
    }
    __syncthreads();

    // normalized recurrent weights + per-row constants -> SMEM (not regs)
    float2 alA, alB;   // init-scope only
    {
        ((float2*)s_wzA)[tid] = make_float2(vzA.x * s_sc[0], vzA.y * s_sc[0]);
        ((float2*)s_wdA)[tid] = make_float2(vdA.x * s_sc[2], vdA.y * s_sc[2]);
        ((float2*)s_wzB)[tid] = make_float2(vzB.x * s_sc[3], vzB.y * s_sc[3]);
        ((float2*)s_wdB)[tid] = make_float2(vdB.x * s_sc[5], vdB.y * s_sc[5]);
        alA = ((const float2*)(alpha + iA * Hd))[tid];
        alB = ((const float2*)(alpha + iB * Hd))[tid];
        ((float2*)s_alA)[tid] = alA;
        ((float2*)s_alB)[tid] = alB;
        ((float2*)s_wvA)[tid] = ((const float2*)(modU_w + iA * Hd))[tid];
        ((float2*)s_wvB)[tid] = ((const float2*)(modU_w + iB * Hd))[tid];
        ((float2*)s_bvA)[tid] = ((const float2*)(modU_b + iA * Hd))[tid];
        ((float2*)s_bvB)[tid] = ((const float2*)(modU_b + iB * Hd))[tid];
        float wrx = vrA.x * s_sc[1], wry = vrA.y * s_sc[1];
        float ax = alA.x + 1e-5f, ay = alA.y + 1e-5f;
        ((float2*)s_upA)[tid] = make_float2(fmaxf(1.f - wrx, 0.f) / ax,
                                            fmaxf(1.f - wry, 0.f) / ay);
        ((float2*)s_loA)[tid] = make_float2(-fmaxf(1.f + wrx, 0.f) / ax,
                                            -fmaxf(1.f + wry, 0.f) / ay);
        wrx = vrB.x * s_sc[4]; wry = vrB.y * s_sc[4];
        ax = alB.x + 1e-5f; ay = alB.y + 1e-5f;
        ((float2*)s_upB)[tid] = make_float2(fmaxf(1.f - wrx, 0.f) / ax,
                                            fmaxf(1.f - wry, 0.f) / ay);
        ((float2*)s_loB)[tid] = make_float2(-fmaxf(1.f + wrx, 0.f) / ax,
                                            -fmaxf(1.f + wry, 0.f) / ay);
    }

    // ---- init state: hj (h regs), te, dU/tE, dvacc ----
    float2 te[8], hj[8], dUB[8], tEB[8];
#pragma unroll
    for (int u = 0; u < 8; u++) {
        float2 dA = ((const float2*)(dU0 + (u * Hd + iA) * Hd))[tid];
        ((float2*)sdU)[u * 256 + tid] = dA;
        ((float2*)stE)[u * 256 + tid] = ((const float2*)(tE0 + (u * Hd + iA) * Hd))[tid];
        dUB[u] = ((const float2*)(dU0 + (u * Hd + iB) * Hd))[tid];
        tEB[u] = ((const float2*)(tE0 + (u * Hd + iB) * Hd))[tid];
        te[u] = ((const float2*)(te0 + u * Hd))[tid];
        hj[u] = ((const float2*)(h0 + u * Hd))[tid];
        float accA = alA.x * dA.x * hj[u].x + alA.y * dA.y * hj[u].y;
        float accB = alB.x * dUB[u].x * hj[u].x + alB.y * dUB[u].y * hj[u].y;
#pragma unroll
        for (int o = 16; o; o >>= 1) {
            accA += __shfl_xor_sync(0xffffffffu, accA, o);
            accB += __shfl_xor_sync(0xffffffffu, accB, o);
        }
        if (lane == 0) { s_redA[wb][u] = accA; s_redA[wb][8 + u] = accB; }
    }
    if (tid < 16) sv[tid] = v0[(tid & 7) * Hd + ((tid < 8) ? iA : iB)];
    __syncthreads();
    if (tid < 16) {
        float s = 0.f;
#pragma unroll
        for (int w2 = 0; w2 < 8; w2++) s += s_redA[w2][tid];
        s_dvacc[tid] = s;
    }
    __syncthreads();

    for (int t = 0; t < Td; t++) {
        float* hn_buf = g_hbuf[t & 1];

        // ---- phase A: block-reduced dots; weights loaded from SMEM ----
        {
            float2 wz2 = ((const float2*)s_wzA)[tid];
            float2 wd2 = ((const float2*)s_wdA)[tid];
            float pz[8], pd[8];
#pragma unroll
            for (int u = 0; u < 8; u++) {
                pz[u] = wz2.x * hj[u].x + wz2.y * hj[u].y;
                pd[u] = wd2.x * hj[u].x + wd2.y * hj[u].y;
            }
#pragma unroll
            for (int o = 16; o; o >>= 1) {
#pragma unroll
                for (int u = 0; u < 8; u++) {
                    pz[u] += __shfl_xor_sync(0xffffffffu, pz[u], o);
                    pd[u] += __shfl_xor_sync(0xffffffffu, pd[u], o);
                }
            }
            if (lane == 0) {
#pragma unroll
                for (int u = 0; u < 8; u++) {
                    s_redA[wb][u] = pz[u]; s_redA[wb][8 + u] = pd[u];
                }
            }
            // pass B (reuse regs)
            wz2 = ((const float2*)s_wzB)[tid];
            wd2 = ((const float2*)s_wdB)[tid];
#pragma unroll
            for (int u = 0; u < 8; u++) {
                pz[u] = wz2.x * hj[u].x + wz2.y * hj[u].y;
                pd[u] = wd2.x * hj[u].x + wd2.y * hj[u].y;
            }
#pragma unroll
            for (int o = 16; o; o >>= 1) {
#pragma unroll
                for (int u = 0; u < 8; u++) {
                    pz[u] += __shfl_xor_sync(0xffffffffu, pz[u], o);
                    pd[u] += __shfl_xor_sync(0xffffffffu, pd[u], o);
                }
            }
            if (lane == 0) {
#pragma unroll
                for (int u = 0; u < 8; u++) {
                    s_redB[wb][u] = pz[u]; s_redB[wb][8 + u] = pd[u];
                }
            }
        }
        __syncthreads();
        if (tid < 8) {
            int b = tid;
            float az = 0.f, ad = 0.f;
#pragma unroll
            for (int w2 = 0; w2 < 8; w2++) { az += s_redA[w2][b]; ad += s_redA[w2][8 + b]; }
            const float* xp = s_xp + (t * Bd + b) * 4;
            float z  = sigf(xp[0] + az + s_bias[0]);
            float dv = xp[1] + ad + s_bias[1] + s_dvacc[b];
            float vo = sv[b];
            float vn = vo + z * (dv - vo);
            sv[b] = vn;
            float hn = fmaxf(vn, 0.f);
            s_hniA[b] = hn;
            hn_buf[b * Hd + iA] = hn;
            out[OFF_OUTS + (t * Bd + b) * Hd + iA] = hn;
        } else if (tid < 16) {
            int b = tid - 8;
            float az = 0.f, ad = 0.f;
#pragma unroll
            for (int w2 = 0; w2 < 8; w2++) { az += s_redB[w2][b]; ad += s_redB[w2][8 + b]; }
            const float* xp = s_xp + (t * Bd + b) * 4;
            float z  = sigf(xp[2] + az + s_bias[2]);
            float dv = xp[3] + ad + s_bias[3] + s_dvacc[8 + b];
            float vo = sv[8 + b];
            float vn = vo + z * (dv - vo);
            sv[8 + b] = vn;
            float hn = fmaxf(vn, 0.f);
            s_hniB[b] = hn;
            hn_buf[b * Hd + iB] = hn;
            out[OFF_OUTS + (t * Bd + b) * Hd + iB] = hn;
        }
        __syncthreads();
        // combined gate contribution (one atomic per gate slot per block)
        if (tid < 32) {
            int bb = tid >> 2, g = tid & 3;
            float v = s_mw8[g] * s_hniA[bb] + s_mw8[4 + g] * s_hniB[bb];
            atomicAdd(&g_gates[t & 3][tid], v);
        }

        grid_bar(lgen, fidx);

        // ---- gates: read finished sums, apply activations ----
        if (tid < 32) {
            float v = __ldcg(&g_gates[t & 3][tid]) + s_mb[tid & 3];
            s_g[tid] = ((tid & 3) == 3) ? fmaxf(v, 0.f) : sigf(v);
        }
        if (iA == 0 && tid >= 64 && tid < 96)
            g_gates[(t + 2) & 3][tid - 64] = 0.f;
        __syncthreads();   // s_g ready

        // ---- te update with OLD hj ----
#pragma unroll
        for (int u = 0; u < 8; u++) {
            float taue = s_g[u * 4 + 0];
            te[u].x += taue * (hj[u].x - te[u].x);
            te[u].y += taue * (hj[u].y - te[u].y);
        }
        if (tid == (iA >> 1)) {
#pragma unroll
            for (int u = 0; u < 8; u++)
                s_teiA[u] = (iA & 1) ? te[u].y : te[u].x;
        }
        if (tid == (iB >> 1)) {
#pragma unroll
            for (int u = 0; u < 8; u++)
                s_teiB[u] = (iB & 1) ? te[u].y : te[u].x;
        }
        // ---- reload hj = new hn (8 independent L2 loads, MLP-hidden) ----
#pragma unroll
        for (int u = 0; u < 8; u++)
            hj[u] = __ldcg((const float2*)(hn_buf + u * Hd) + tid);
        __syncthreads();   // s_tei ready

        // ---- main state update (row A smem, row B regs) + fused matvec ----
        {
            float2 wA = ((const float2*)s_wvA)[tid];
            float2 bA = ((const float2*)s_bvA)[tid];
            float2 wB = ((const float2*)s_wvB)[tid];
            float2 bB = ((const float2*)s_bvB)[tid];
            float2 aA = ((const float2*)s_alA)[tid];
            float2 aB = ((const float2*)s_alB)[tid];
            float2 lA = ((const float2*)s_loA)[tid];
            float2 uA = ((const float2*)s_upA)[tid];
            float2 lB = ((const float2*)s_loB)[tid];
            float2 uB = ((const float2*)s_upB)[tid];
#pragma unroll
            for (int u = 0; u < 8; u++) {
                float2 hnj = hj[u];
                float tauE = s_g[u * 4 + 1], tauU = s_g[u * 4 + 2], mU = s_g[u * 4 + 3];
                float2 tn = te[u];
                // row A (state in smem)
                float hni = s_hniA[u], tei = s_teiA[u];
                float ox = hni * tn.x - tei * hnj.x;
                float oy = hni * tn.y - tei * hnj.y;
                float2 E = ((float2*)stE)[u * 256 + tid];
                E.x += tauE * (ox - E.x);
                E.y += tauE * (oy - E.y);
                ((float2*)stE)[u * 256 + tid] = E;
                float2 D = ((float2*)sdU)[u * 256 + tid];
                D.x += tauU * (sshr(fmaf(mU, wA.x, bA.x)) * E.x - D.x);
                D.y += tauU * (sshr(fmaf(mU, wA.y, bA.y)) * E.y - D.y);
                D.x = fminf(fmaxf(D.x, lA.x), uA.x);
                D.y = fminf(fmaxf(D.y, lA.y), uA.y);
                ((float2*)sdU)[u * 256 + tid] = D;
                float accA = aA.x * D.x * hnj.x + aA.y * D.y * hnj.y;
                // row B (state in registers)
                hni = s_hniB[u]; tei = s_teiB[u];
                ox = hni * tn.x - tei * hnj.x;
                oy = hni * tn.y - tei * hnj.y;
                tEB[u].x += tauE * (ox - tEB[u].x);
                tEB[u].y += tauE * (oy - tEB[u].y);
                dUB[u].x += tauU * (sshr(fmaf(mU, wB.x, bB.x)) * tEB[u].x - dUB[u].x);
                dUB[u].y += tauU * (sshr(fmaf(mU, wB.y, bB.y)) * tEB[u].y - dUB[u].y);
                dUB[u].x = fminf(fmaxf(dUB[u].x, lB.x), uB.x);
                dUB[u].y = fminf(fmaxf(dUB[u].y, lB.y), uB.y);
                float accB = aB.x * dUB[u].x * hnj.x + aB.y * dUB[u].y * hnj.y;
#pragma unroll
                for (int o = 16; o; o >>= 1) {
                    accA += __shfl_xor_sync(0xffffffffu, accA, o);
                    accB += __shfl_xor_sync(0xffffffffu, accB, o);
                }
                if (lane == 0) { s_redA[wb][u] = accA; s_redA[wb][8 + u] = accB; }
            }
        }
        __syncthreads();
        if (tid < 16) {
            float s = 0.f;
#pragma unroll
            for (int w2 = 0; w2 < 8; w2++) s += s_redA[w2][tid];
            s_dvacc[tid] = s;
        }
        __syncthreads();
    }

    // ---- epilogue: dump final state ----
    if (tid < 16) {
        int b = tid & 7, col = (tid < 8) ? iA : iB;
        out[OFF_V + b * Hd + col] = sv[tid];
        out[OFF_H + b * Hd + col] = (tid < 8) ? s_hniA[b] : s_hniB[b];
    }
#pragma unroll
    for (int u = 0; u < 8; u++) {
        ((float2*)(out + OFF_DU  + (u * Hd + iA) * Hd))[tid] = ((float2*)sdU)[u * 256 + tid];
        ((float2*)(out + OFF_TEE + (u * Hd + iA) * Hd))[tid] = ((float2*)stE)[u * 256 + tid];
        ((float2*)(out + OFF_DU  + (u * Hd + iB) * Hd))[tid] = dUB[u];
        ((float2*)(out + OFF_TEE + (u * Hd + iB) * Hd))[tid] = tEB[u];
    }
    if (iA == 0) {
#pragma unroll
        for (int u = 0; u < 8; u++)
            ((float2*)(out + OFF_TE + u * Hd))[tid] = te[u];
    }
}

extern "C" void kernel_launch(void* const* d_in, const int* in_sizes, int n_in,
                              void* d_out, int out_size) {
    const float* x       = (const float*)d_in[0];
    const float* h0      = (const float*)d_in[1];
    const float* v0      = (const float*)d_in[2];
    const float* dU0     = (const float*)d_in[3];
    const float* te0     = (const float*)d_in[4];
    const float* tE0     = (const float*)d_in[5];
    const float* x2h_v   = (const float*)d_in[6];
    const float* x2h_g   = (const float*)d_in[7];
    const float* x2h_b   = (const float*)d_in[8];
    const float* h2h_v   = (const float*)d_in[9];
    const float* h2h_g   = (const float*)d_in[10];
    const float* h2h_b   = (const float*)d_in[11];
    const float* alpha   = (const float*)d_in[12];
    const float* h2mod_w = (const float*)d_in[13];
    const float* h2mod_b = (const float*)d_in[14];
    const float* modU_w  = (const float*)d_in[15];
    const float* modU_b  = (const float*)d_in[16];
    float* out = (float*)d_out;

    const int scan_smem = 16384 * sizeof(float); // 65536 B
    cudaFuncSetAttribute(k_scan, cudaFuncAttributeMaxDynamicSharedMemorySize, scan_smem);

    k_xproj<<<dim3(4, 32), 256>>>(x, x2h_v, x2h_g, x2h_b);
    k_scan<<<NBLK, 256, scan_smem>>>(h0, v0, dU0, te0, tE0, alpha,
                                     h2h_v, h2h_g, h2h_b,
                                     h2mod_w, h2mod_b, modU_w, modU_b, out);
}